// round 16
// baseline (speedup 1.0000x reference)
#include <cuda_runtime.h>
#include <cstdint>

// Problem constants (fixed by setup_inputs)
#define BD   4
#define NH   4
#define HD   8
#define HH   256
#define WW   256
#define KS   5
#define AMP  2

// Tiling: 32x16 tile, 256 threads, 2 pixels per thread, ONE HEAD PER BLOCK
#define TILE_Y 16
#define TILE_X 32
#define TXN    16
#define P      2
#define NTHR   256
#define SROWS  (TILE_Y + 2*AMP)   // 20
#define SCOLS_S 36                // 144B row
#define CHELEMS_S (SROWS * SCOLS_S)  // 720
#define NROWS  (HD * SROWS)       // 160

__device__ __forceinline__ uint32_t smem_u32(const void* p) {
    uint32_t a;
    asm("{ .reg .u64 t; cvta.to.shared.u64 t, %1; cvt.u32.u64 %0, t; }"
        : "=r"(a) : "l"(p));
    return a;
}
__device__ __forceinline__ float ex2f(float x) {
    float r; asm("ex2.approx.f32 %0, %1;" : "=f"(r) : "f"(x)); return r;
}
__device__ __forceinline__ float rcpf(float x) {
    float r; asm("rcp.approx.f32 %0, %1;" : "=f"(r) : "f"(x)); return r;
}
__device__ __forceinline__ void cp8(uint32_t s, const float* g) {
    asm volatile("cp.async.ca.shared.global [%0], [%1], 8;"
                 :: "r"(s), "l"(g));
}
__device__ __forceinline__ void redadd(float* p, float v) {
    asm volatile("red.global.add.f32 [%0], %1;" :: "l"(p), "f"(v) : "memory");
}
__device__ __forceinline__ int clampi(int v, int lo, int hi) {
    return min(max(v, lo), hi);
}

// Clamp-address staging: out-of-image slots hold nearby real (finite) k
// values that are never consumed (their softmax weights are masked to 0).
__device__ __forceinline__ void stage_head(uint32_t sbase,
                                           const float* __restrict__ xk_b,
                                           int h, int x0, int y0, int tid)
{
    // interior: m = 2,4,...,32 -> 16 cp8/row; 160 rows * 16 = 2560 = 10 iters
    #pragma unroll
    for (int it = 0; it < 10; ++it) {
        int idx = it * NTHR + tid;
        int row = idx >> 4;               // 0..159
        int e   = idx & 15;               // 0..15
        int m   = 2 + 2 * e;              // 2,4,...,32
        int c   = row / SROWS;
        int r   = row - c * SROWS;
        int gy  = clampi(y0 - AMP + r, 0, HH - 1);
        int gx  = x0 - AMP + m;           // always in-image in x
        const float* g = xk_b + ((c * NH + h) << 16) + (gy << 8) + gx;
        cp8(sbase + (uint32_t)(c * CHELEMS_S + r * SCOLS_S + m) * 4u, g);
    }
    // edges: cols {0,1} and {34,35} as one cp8 each (gmem clamped even;
    // exact whenever consumable). 160 rows * 2 = 320 ops -> 2 iterations.
    #pragma unroll
    for (int it = 0; it < 2; ++it) {
        int idx = it * NTHR + tid;
        if (it == 1 && idx >= NROWS * 2) break;
        int row = idx >> 1;               // 0..159
        int e   = idx & 1;                // 0: left pair, 1: right pair
        int m   = e ? 34 : 0;
        int c   = row / SROWS;
        int r   = row - c * SROWS;
        int gy  = clampi(y0 - AMP + r, 0, HH - 1);
        int gx  = e ? min(x0 + 32, WW - 2) : max(x0 - 2, 0);  // even by constr.
        const float* g = xk_b + ((c * NH + h) << 16) + (gy << 8) + gx;
        cp8(sbase + (uint32_t)(c * CHELEMS_S + r * SCOLS_S + m) * 4u, g);
    }
    asm volatile("cp.async.commit_group;" ::: "memory");
}

__global__ __launch_bounds__(NTHR, 4)
void cover_kernel(const float* __restrict__ xq,
                  const float* __restrict__ xk,
                  float* __restrict__ out)
{
    // single per-head k tile: 8ch x 20 x 36 floats = 23040 B
    __shared__ __align__(16) float sk[HD][SROWS][SCOLS_S];

    const int tid = threadIdx.x;
    const int tx  = tid & (TXN - 1);   // 0..15
    const int ty  = tid >> 4;          // 0..15
    const int x0  = blockIdx.x * TILE_X;
    const int y0  = blockIdx.y * TILE_Y;
    const int bz  = blockIdx.z;        // 0..15
    const int b   = bz >> 2;
    const int h   = bz & 3;
    const int y   = y0 + ty;
    const int xg  = x0 + tx * P;

    const uint32_t sb = smem_u32(&sk[0][0][0]);
    const long plane = (long)HH * WW;
    const float* xq_b = xq + (long)b * (NH * HD) * plane;
    const float* xk_b = xk + (long)b * (NH * HD) * plane;

    // kick off this head's staging immediately
    stage_head(sb, xk_b, h, x0, y0, tid);

    // validity bitmasks (di/dj in 0..4 -> spatial offset -2..+2)
    unsigned rowbits = 0;
    #pragma unroll
    for (int di = 0; di < KS; ++di) {
        int yy = y + di - AMP;
        if (yy >= 0 && yy < HH) rowbits |= (1u << di);
    }
    unsigned colbits[P];
    #pragma unroll
    for (int p = 0; p < P; ++p) {
        unsigned cb = 0;
        #pragma unroll
        for (int dj = 0; dj < KS; ++dj) {
            int xx = xg + p + dj - AMP;
            if (xx >= 0 && xx < WW) cb |= (1u << dj);
        }
        colbits[p] = cb;
    }
    const bool allvalid = (rowbits == 0x1Fu) &&
        ((colbits[0] & colbits[1]) == 0x1Fu);

    // q preload (gmem, independent of smem): overlaps the cp.async wait
    const float qscale = 0.35355339059327373f * 1.4426950408889634f;
    float q[HD][P];
    #pragma unroll
    for (int c = 0; c < HD; ++c) {
        float2 qv = *reinterpret_cast<const float2*>(
            xq_b + ((c * NH + h) << 16) + (y << 8) + xg);
        q[c][0] = qv.x * qscale;
        q[c][1] = qv.y * qscale;
    }

    asm volatile("cp.async.wait_group 0;" ::: "memory");
    __syncthreads();   // the ONLY barrier in the kernel

    const float* kb = &sk[0][ty][tx * P];

    float s[P]  = {0.f, 0.f};
    float oy[P] = {0.f, 0.f};
    float ox[P] = {0.f, 0.f};

    #pragma unroll
    for (int di = 0; di < KS; ++di) {
        float a[KS][P];
        #pragma unroll
        for (int dj = 0; dj < KS; ++dj)
            #pragma unroll
            for (int p = 0; p < P; ++p) a[dj][p] = 0.f;

        // software-pipelined channel loop: channel c+1's k loads issue
        // BEFORE channel c's FMA block consumes its values
        const float* kr0 = kb + di * SCOLS_S;
        float2 k01 = *reinterpret_cast<const float2*>(kr0);
        float2 k23 = *reinterpret_cast<const float2*>(kr0 + 2);
        float2 k45 = *reinterpret_cast<const float2*>(kr0 + 4);
        #pragma unroll
        for (int c = 0; c < HD; ++c) {
            float2 c01 = k01, c23 = k23, c45 = k45;
            if (c + 1 < HD) {
                const float* kr = kb + (c + 1) * CHELEMS_S + di * SCOLS_S;
                k01 = *reinterpret_cast<const float2*>(kr);
                k23 = *reinterpret_cast<const float2*>(kr + 2);
                k45 = *reinterpret_cast<const float2*>(kr + 4);
            }
            float kk[6] = {c01.x, c01.y, c23.x, c23.y, c45.x, c45.y};
            #pragma unroll
            for (int dj = 0; dj < KS; ++dj)
                #pragma unroll
                for (int p = 0; p < P; ++p)
                    a[dj][p] = fmaf(q[c][p], kk[p + dj], a[dj][p]);
        }

        const float fdi = (float)(di - AMP);
        if (allvalid) {
            #pragma unroll
            for (int p = 0; p < P; ++p) {
                float w0 = ex2f(a[0][p]);
                float w1 = ex2f(a[1][p]);
                float w2 = ex2f(a[2][p]);
                float w3 = ex2f(a[3][p]);
                float w4 = ex2f(a[4][p]);
                float rs = ((w0 + w1) + (w2 + w3)) + w4;
                float cs = fmaf(2.f, w4 - w0, w3 - w1);
                s[p]  += rs;
                if (di != 2) oy[p] = fmaf(rs, fdi, oy[p]);
                ox[p] += cs;
            }
        } else {
            const bool rvalid = (rowbits >> di) & 1u;
            #pragma unroll
            for (int p = 0; p < P; ++p) {
                const unsigned cb = colbits[p];
                float w[KS];
                #pragma unroll
                for (int dj = 0; dj < KS; ++dj) {
                    bool valid = rvalid && ((cb >> dj) & 1u);
                    w[dj] = valid ? ex2f(a[dj][p]) : 0.f;
                }
                float rs = ((w[0] + w[1]) + (w[2] + w[3])) + w[4];
                float cs = fmaf(2.f, w[4] - w[0], w[3] - w[1]);
                s[p]  += rs;
                if (di != 2) oy[p] = fmaf(rs, fdi, oy[p]);
                ox[p] += cs;
            }
        }
    }

    // this head's contribution (1/NH of the mean), atomically accumulated
    const float invh = 1.0f / (float)NH;
    float* ob = out + (long)b * 2 * plane + (y << 8) + xg;
    #pragma unroll
    for (int p = 0; p < P; ++p) {
        float inv = rcpf(s[p]) * invh;
        redadd(ob + p,         oy[p] * inv);
        redadd(ob + plane + p, ox[p] * inv);
    }
}

extern "C" void kernel_launch(void* const* d_in, const int* in_sizes, int n_in,
                              void* d_out, int out_size)
{
    const float* xq = (const float*)d_in[0];
    const float* xk = (const float*)d_in[1];
    float* out = (float*)d_out;
    (void)in_sizes; (void)n_in;

    // zero the accumulator (graph-capturable async memset)
    cudaMemsetAsync(d_out, 0, (size_t)out_size * sizeof(float), 0);

    dim3 grid(WW / TILE_X, HH / TILE_Y, BD * NH);  // (8, 16, 16) = 2048 blocks
    cover_kernel<<<grid, NTHR>>>(xq, xk, out);
}

// round 17
// speedup vs baseline: 1.0779x; 1.0779x over previous
#include <cuda_runtime.h>
#include <cstdint>

// Problem constants (fixed by setup_inputs)
#define BD   4
#define NH   4
#define HD   8
#define HH   256
#define WW   256
#define KS   5
#define AMP  2

// Tiling: 32x8 tile, 128 threads, 2 pixels per thread, ONE HEAD PER BLOCK
#define TILE_Y 8
#define TILE_X 32
#define TXN    16
#define P      2
#define NTHR   128
#define SROWS  (TILE_Y + 2*AMP)   // 12
#define SCOLS_S 36                // 144B row
#define CHELEMS_S (SROWS * SCOLS_S)  // 432
#define NROWS  (HD * SROWS)       // 96

__device__ __forceinline__ uint32_t smem_u32(const void* p) {
    uint32_t a;
    asm("{ .reg .u64 t; cvta.to.shared.u64 t, %1; cvt.u32.u64 %0, t; }"
        : "=r"(a) : "l"(p));
    return a;
}
__device__ __forceinline__ float ex2f(float x) {
    float r; asm("ex2.approx.f32 %0, %1;" : "=f"(r) : "f"(x)); return r;
}
__device__ __forceinline__ float rcpf(float x) {
    float r; asm("rcp.approx.f32 %0, %1;" : "=f"(r) : "f"(x)); return r;
}
__device__ __forceinline__ void cp8(uint32_t s, const float* g) {
    asm volatile("cp.async.ca.shared.global [%0], [%1], 8;"
                 :: "r"(s), "l"(g));
}
__device__ __forceinline__ void redadd(float* p, float v) {
    asm volatile("red.global.add.f32 [%0], %1;" :: "l"(p), "f"(v) : "memory");
}
__device__ __forceinline__ int clampi(int v, int lo, int hi) {
    return min(max(v, lo), hi);
}

// Clamp-address staging: out-of-image slots hold nearby real (finite) k
// values that are never consumed (their softmax weights are masked to 0).
__device__ __forceinline__ void stage_head(uint32_t sbase,
                                           const float* __restrict__ xk_b,
                                           int h, int x0, int y0, int tid)
{
    #pragma unroll
    for (int it = 0; it < 12; ++it) {
        int idx = it * NTHR + tid;
        int row = idx >> 4;               // 0..95
        int e   = idx & 15;               // 0..15
        int m   = 2 + 2 * e;              // 2,4,...,32
        int c   = row / SROWS;
        int r   = row - c * SROWS;
        int gy  = clampi(y0 - AMP + r, 0, HH - 1);
        int gx  = x0 - AMP + m;           // always in-image in x
        const float* g = xk_b + ((c * NH + h) << 16) + (gy << 8) + gx;
        cp8(sbase + (uint32_t)(c * CHELEMS_S + r * SCOLS_S + m) * 4u, g);
    }
    #pragma unroll
    for (int it = 0; it < 2; ++it) {
        int idx = it * NTHR + tid;
        if (it == 1 && idx >= NROWS * 2) break;
        int row = idx >> 1;
        int e   = idx & 1;                // 0: left pair, 1: right pair
        int m   = e ? 34 : 0;
        int c   = row / SROWS;
        int r   = row - c * SROWS;
        int gy  = clampi(y0 - AMP + r, 0, HH - 1);
        int gx  = e ? min(x0 + 32, WW - 2) : max(x0 - 2, 0);  // even by constr.
        const float* g = xk_b + ((c * NH + h) << 16) + (gy << 8) + gx;
        cp8(sbase + (uint32_t)(c * CHELEMS_S + r * SCOLS_S + m) * 4u, g);
    }
    asm volatile("cp.async.commit_group;" ::: "memory");
}

__global__ __launch_bounds__(NTHR, 8)
void cover_kernel(const float* __restrict__ xq,
                  const float* __restrict__ xk,
                  float* __restrict__ out)
{
    // single per-head k tile: 8ch x 12 x 36 floats = 13824 B
    __shared__ __align__(16) float sk[HD][SROWS][SCOLS_S];

    const int tid = threadIdx.x;
    const int tx  = tid & (TXN - 1);   // 0..15
    const int ty  = tid >> 4;          // 0..7
    const int x0  = blockIdx.x * TILE_X;
    const int y0  = blockIdx.y * TILE_Y;
    const int bz  = blockIdx.z;        // 0..15
    const int b   = bz >> 2;
    const int h   = bz & 3;
    const int y   = y0 + ty;
    const int xg  = x0 + tx * P;

    const uint32_t sb = smem_u32(&sk[0][0][0]);
    const long plane = (long)HH * WW;
    const float* xq_b = xq + (long)b * (NH * HD) * plane;
    const float* xk_b = xk + (long)b * (NH * HD) * plane;

    // kick off this head's staging immediately
    stage_head(sb, xk_b, h, x0, y0, tid);

    // validity bitmasks (di/dj in 0..4 -> spatial offset -2..+2)
    unsigned rowbits = 0;
    #pragma unroll
    for (int di = 0; di < KS; ++di) {
        int yy = y + di - AMP;
        if (yy >= 0 && yy < HH) rowbits |= (1u << di);
    }
    unsigned colbits[P];
    #pragma unroll
    for (int p = 0; p < P; ++p) {
        unsigned cb = 0;
        #pragma unroll
        for (int dj = 0; dj < KS; ++dj) {
            int xx = xg + p + dj - AMP;
            if (xx >= 0 && xx < WW) cb |= (1u << dj);
        }
        colbits[p] = cb;
    }
    const bool allvalid = (rowbits == 0x1Fu) &&
        ((colbits[0] & colbits[1]) == 0x1Fu);

    // q preload (gmem, independent of smem): overlaps the cp.async wait
    const float qscale = 0.35355339059327373f * 1.4426950408889634f;
    float q[HD][P];
    #pragma unroll
    for (int c = 0; c < HD; ++c) {
        float2 qv = *reinterpret_cast<const float2*>(
            xq_b + ((c * NH + h) << 16) + (y << 8) + xg);
        q[c][0] = qv.x * qscale;
        q[c][1] = qv.y * qscale;
    }

    asm volatile("cp.async.wait_group 0;" ::: "memory");
    __syncthreads();   // the ONLY barrier in the kernel

    const float* kb = &sk[0][ty][tx * P];

    float s[P]  = {0.f, 0.f};
    float oy[P] = {0.f, 0.f};
    float ox[P] = {0.f, 0.f};

    #pragma unroll
    for (int di = 0; di < KS; ++di) {
        float a[KS][P];
        #pragma unroll
        for (int dj = 0; dj < KS; ++dj)
            #pragma unroll
            for (int p = 0; p < P; ++p) a[dj][p] = 0.f;

        // A/B register double-buffered channel loop: NO copy MOVs.
        // Load B[c+1] -> FMA A[c] -> load A[c+2] -> FMA B[c+1], alternating.
        const float* kr = kb + di * SCOLS_S;
        float2 A0 = *reinterpret_cast<const float2*>(kr);
        float2 A1 = *reinterpret_cast<const float2*>(kr + 2);
        float2 A2 = *reinterpret_cast<const float2*>(kr + 4);
        float2 B0, B1, B2;
        #pragma unroll
        for (int c = 0; c < HD; c += 2) {
            kr = kb + (c + 1) * CHELEMS_S + di * SCOLS_S;
            B0 = *reinterpret_cast<const float2*>(kr);
            B1 = *reinterpret_cast<const float2*>(kr + 2);
            B2 = *reinterpret_cast<const float2*>(kr + 4);
            {
                float kk[6] = {A0.x, A0.y, A1.x, A1.y, A2.x, A2.y};
                #pragma unroll
                for (int dj = 0; dj < KS; ++dj)
                    #pragma unroll
                    for (int p = 0; p < P; ++p)
                        a[dj][p] = fmaf(q[c][p], kk[p + dj], a[dj][p]);
            }
            if (c + 2 < HD) {
                kr = kb + (c + 2) * CHELEMS_S + di * SCOLS_S;
                A0 = *reinterpret_cast<const float2*>(kr);
                A1 = *reinterpret_cast<const float2*>(kr + 2);
                A2 = *reinterpret_cast<const float2*>(kr + 4);
            }
            {
                float kk[6] = {B0.x, B0.y, B1.x, B1.y, B2.x, B2.y};
                #pragma unroll
                for (int dj = 0; dj < KS; ++dj)
                    #pragma unroll
                    for (int p = 0; p < P; ++p)
                        a[dj][p] = fmaf(q[c + 1][p], kk[p + dj], a[dj][p]);
            }
        }

        const float fdi = (float)(di - AMP);
        if (allvalid) {
            #pragma unroll
            for (int p = 0; p < P; ++p) {
                float w0 = ex2f(a[0][p]);
                float w1 = ex2f(a[1][p]);
                float w2 = ex2f(a[2][p]);
                float w3 = ex2f(a[3][p]);
                float w4 = ex2f(a[4][p]);
                float rs = ((w0 + w1) + (w2 + w3)) + w4;
                float cs = fmaf(2.f, w4 - w0, w3 - w1);
                s[p]  += rs;
                if (di != 2) oy[p] = fmaf(rs, fdi, oy[p]);
                ox[p] += cs;
            }
        } else {
            const bool rvalid = (rowbits >> di) & 1u;
            #pragma unroll
            for (int p = 0; p < P; ++p) {
                const unsigned cb = colbits[p];
                float w[KS];
                #pragma unroll
                for (int dj = 0; dj < KS; ++dj) {
                    bool valid = rvalid && ((cb >> dj) & 1u);
                    w[dj] = valid ? ex2f(a[dj][p]) : 0.f;
                }
                float rs = ((w[0] + w[1]) + (w[2] + w[3])) + w[4];
                float cs = fmaf(2.f, w[4] - w[0], w[3] - w[1]);
                s[p]  += rs;
                if (di != 2) oy[p] = fmaf(rs, fdi, oy[p]);
                ox[p] += cs;
            }
        }
    }

    // this head's contribution (1/NH of the mean), atomically accumulated
    const float invh = 1.0f / (float)NH;
    float* ob = out + (long)b * 2 * plane + (y << 8) + xg;
    #pragma unroll
    for (int p = 0; p < P; ++p) {
        float inv = rcpf(s[p]) * invh;
        redadd(ob + p,         oy[p] * inv);
        redadd(ob + plane + p, ox[p] * inv);
    }
}

extern "C" void kernel_launch(void* const* d_in, const int* in_sizes, int n_in,
                              void* d_out, int out_size)
{
    const float* xq = (const float*)d_in[0];
    const float* xk = (const float*)d_in[1];
    float* out = (float*)d_out;
    (void)in_sizes; (void)n_in;

    // zero the accumulator (graph-capturable async memset)
    cudaMemsetAsync(d_out, 0, (size_t)out_size * sizeof(float), 0);

    dim3 grid(WW / TILE_X, HH / TILE_Y, BD * NH);  // (8, 32, 16) = 4096 blocks
    cover_kernel<<<grid, NTHR>>>(xq, xk, out);
}